// round 9
// baseline (speedup 1.0000x reference)
#include <cuda_runtime.h>
#include <cuda_fp16.h>
#include <cstdint>

// Problem constants
#define BATCH   32
#define HID     1024
#define NGATE   4096          // 4*HID
#define TSTEPS  511           // T-1
#define MTOT    16352         // TSTEPS*BATCH
#define RES_ELEMS (511*32*1024)

#define NCTA    64            // lstm CTAs; CTA owns 16 hidden units
#define NTHR    512

// ---------------- device scratch (no runtime allocation allowed) -------------
__device__ float    g_xp[(size_t)MTOT * NGATE];    // x-projection (+bias), fp32
__device__ unsigned g_hp[2][64 * 32 * 8];          // h double-buffered, fp16 frag-packed
__device__ unsigned g_cnt1[8 * 32];                // level-1 arrival counters, 128B apart
__device__ unsigned g_cnt2;                        // level-2 counter
__device__ unsigned g_epoch;                       // released epoch (monotonic across replays)

// ---------------- small helpers ----------------------------------------------
__device__ __forceinline__ unsigned f2tf(float f) {
    unsigned u;
    asm("cvt.rna.tf32.f32 %0, %1;" : "=r"(u) : "f"(f));
    return u;
}
__device__ __forceinline__ uint4 ldcg4(const unsigned* p) {
    uint4 v;
    asm volatile("ld.global.cg.v4.u32 {%0,%1,%2,%3}, [%4];"
                 : "=r"(v.x), "=r"(v.y), "=r"(v.z), "=r"(v.w) : "l"(p));
    return v;
}
__device__ __forceinline__ unsigned ldacq(const unsigned* p) {
    unsigned v;
    asm volatile("ld.acquire.gpu.global.u32 %0, [%1];" : "=r"(v) : "l"(p));
    return v;
}
// tf32 mma (xproj)
__device__ __forceinline__ void mma8(float c[4], unsigned a0, unsigned a1, unsigned a2,
                                     unsigned a3, unsigned b0, unsigned b1) {
    asm volatile(
        "mma.sync.aligned.m16n8k8.row.col.f32.tf32.tf32.f32 "
        "{%0,%1,%2,%3}, {%4,%5,%6,%7}, {%8,%9}, {%0,%1,%2,%3};"
        : "+f"(c[0]), "+f"(c[1]), "+f"(c[2]), "+f"(c[3])
        : "r"(a0), "r"(a1), "r"(a2), "r"(a3), "r"(b0), "r"(b1));
}
// fp16 mma (recurrence)
__device__ __forceinline__ void mma16(float c[4], unsigned a0, unsigned a1, unsigned a2,
                                      unsigned a3, unsigned b0, unsigned b1) {
    asm volatile(
        "mma.sync.aligned.m16n8k16.row.col.f32.f16.f16.f32 "
        "{%0,%1,%2,%3}, {%4,%5,%6,%7}, {%8,%9}, {%0,%1,%2,%3};"
        : "+f"(c[0]), "+f"(c[1]), "+f"(c[2]), "+f"(c[3])
        : "r"(a0), "r"(a1), "r"(a2), "r"(a3), "r"(b0), "r"(b1));
}
__device__ __forceinline__ float fsig(float x) {
    return __fdividef(1.f, 1.f + __expf(-x));
}
__device__ __forceinline__ float ftanh(float x) {
    return __fmaf_rn(2.f, fsig(2.f * x), -1.f);
}

// arrival fan-in tree for 64 CTAs: 8 counters x 8 -> cnt2 x 8 -> epoch.
// epoch bumps ONLY after all 64 arrivals => e0 snapshot at kernel start is safe.
__device__ __forceinline__ void bar_arrive(int bid) {
    __threadfence();
    unsigned o1 = atomicAdd(&g_cnt1[(bid & 7) * 32], 1u);
    if ((o1 & 7u) == 7u) {
        unsigned o2 = atomicAdd(&g_cnt2, 1u);
        if ((o2 & 7u) == 7u) atomicAdd(&g_epoch, 1u);
    }
}

// ---------------- x_proj: xp[t*32+b][g] = emb[tgt[b][t]] . W_ih[g] + bias ----
__global__ void __launch_bounds__(256)
xproj_kernel(const int* __restrict__ tgt, const float* __restrict__ emb,
             const float* __restrict__ W, const float* __restrict__ b_ih,
             const float* __restrict__ b_hh)
{
    __shared__ unsigned As[128][32];   // rotated: phys col4 = (c4 + (m&7)) & 7
    __shared__ unsigned Bs[128][32];

    const int nb = blockIdx.x, mb = blockIdx.y;
    const int tid = threadIdx.x, lane = tid & 31, wid = tid >> 5;
    const int warp_m = wid & 1, warp_n = wid >> 1;
    const int c4 = tid & 7, row0 = tid >> 3;
    const int g = lane >> 2, tg = lane & 3;

    int toks[4];
#pragma unroll
    for (int r = 0; r < 4; ++r) {
        int m  = row0 + r * 32;
        int mg = mb * 128 + m;
        int bb = mg & 31, tt = mg >> 5;
        int tok = tgt[bb * 512 + tt];
        toks[r] = (tok < 0 || tok > 31999) ? 0 : tok;
    }

    float acc[4][4][4];
#pragma unroll
    for (int mt = 0; mt < 4; ++mt)
#pragma unroll
        for (int nt = 0; nt < 4; ++nt)
#pragma unroll
            for (int i = 0; i < 4; ++i) acc[mt][nt][i] = 0.f;

    for (int kt = 0; kt < 32; ++kt) {
        const int koff = kt * 32 + c4 * 4;
#pragma unroll
        for (int r = 0; r < 4; ++r) {
            int m = row0 + r * 32;
            float4 va = *(const float4*)(emb + (size_t)toks[r] * 1024 + koff);
            unsigned* da = &As[m][((c4 + m) & 7) * 4];
            da[0] = f2tf(va.x); da[1] = f2tf(va.y); da[2] = f2tf(va.z); da[3] = f2tf(va.w);
            float4 vb = *(const float4*)(W + (size_t)(nb * 128 + m) * 1024 + koff);
            unsigned* db = &Bs[m][((c4 + m) & 7) * 4];
            db[0] = f2tf(vb.x); db[1] = f2tf(vb.y); db[2] = f2tf(vb.z); db[3] = f2tf(vb.w);
        }
        __syncthreads();
#pragma unroll
        for (int ks = 0; ks < 4; ++ks) {
            const int kb = ks * 8;
            unsigned a[4][4], bf[4][2];
#pragma unroll
            for (int mt = 0; mt < 4; ++mt) {
                int m   = warp_m * 64 + mt * 16 + g;
                int rot = 4 * (m & 7);
                a[mt][0] = As[m    ][(kb + tg     + rot) & 31];
                a[mt][1] = As[m + 8][(kb + tg     + rot) & 31];
                a[mt][2] = As[m    ][(kb + tg + 4 + rot) & 31];
                a[mt][3] = As[m + 8][(kb + tg + 4 + rot) & 31];
            }
#pragma unroll
            for (int nt = 0; nt < 4; ++nt) {
                int n   = warp_n * 32 + nt * 8 + g;
                int rot = 4 * (n & 7);
                bf[nt][0] = Bs[n][(kb + tg     + rot) & 31];
                bf[nt][1] = Bs[n][(kb + tg + 4 + rot) & 31];
            }
#pragma unroll
            for (int mt = 0; mt < 4; ++mt)
#pragma unroll
                for (int nt = 0; nt < 4; ++nt)
                    mma8(acc[mt][nt], a[mt][0], a[mt][1], a[mt][2], a[mt][3],
                         bf[nt][0], bf[nt][1]);
        }
        __syncthreads();
    }

#pragma unroll
    for (int mt = 0; mt < 4; ++mt) {
#pragma unroll
        for (int nt = 0; nt < 4; ++nt) {
            int m0 = mb * 128 + warp_m * 64 + mt * 16 + g;
            int n0 = nb * 128 + warp_n * 32 + nt * 8 + tg * 2;
            float bia0 = b_ih[n0] + b_hh[n0];
            float bia1 = b_ih[n0 + 1] + b_hh[n0 + 1];
            if (m0 < MTOT) {
                g_xp[(size_t)m0 * NGATE + n0]     = acc[mt][nt][0] + bia0;
                g_xp[(size_t)m0 * NGATE + n0 + 1] = acc[mt][nt][1] + bia1;
            }
            if (m0 + 8 < MTOT) {
                g_xp[(size_t)(m0 + 8) * NGATE + n0]     = acc[mt][nt][2] + bia0;
                g_xp[(size_t)(m0 + 8) * NGATE + n0 + 1] = acc[mt][nt][3] + bia1;
            }
        }
    }
}

// ---------------- persistent recurrent kernel --------------------------------
// 64 CTAs x 512 threads. CTA c owns hidden units [c*16, c*16+16) == packed-h
// kb-block c (1KB). Warp grid: wk = wid&7 (K slice of 128), wn = wid>>3
// (32 of the 64 local gate-rows). W_hh fp16 fragments in registers.
// Publish: stage fp16 in SMEM -> warp 0 writes the CTA's 1KB block with
// 64 x STG.128 (coalesced) -> lane0 fence + tree arrival (8x8 -> 8 -> epoch).
// Detection: flat, 64 pollers on g_epoch (R6-style, measured best).
__global__ void __launch_bounds__(NTHR, 1)
lstm_kernel(const float* __restrict__ h0, const float* __restrict__ c0,
            const float* __restrict__ W_hh, float* __restrict__ out, int out_size)
{
    extern __shared__ float sh[];
    float*  red   = sh;                          // 32*65*8 = 16640 floats (66560 B)
    __half* stage = (__half*)(sh + 16640);       // 512 halves (1 KB)

    const int tid = threadIdx.x, lane = tid & 31, wid = tid >> 5;
    const int g = lane >> 2, tg = lane & 3;
    const int wk = wid & 7, wn = wid >> 3;
    const int bid = blockIdx.x;
    const int j0 = bid * 16;
    const int b = tid >> 4, u = tid & 15;        // this thread's cell (b, j0+u)

    const unsigned e0 = g_epoch;   // stable: epoch bumps only after ALL 64 arrive

    // ---- load this CTA's W_hh fragments into registers (fp16 pairs) ----
    // warp (wk, wn): K slice [wk*128, +128) = k16 blocks wk*8..+7,
    // gate-rows r = wn*32 + nt*8 + g, r = q*16 + uu (q = gate, uu = local unit)
    unsigned bw[8][4][2];
#pragma unroll
    for (int s = 0; s < 8; ++s) {
#pragma unroll
        for (int nt = 0; nt < 4; ++nt) {
            int r = wn * 32 + nt * 8 + g;
            int q = r >> 4, uu = r & 15;
            const float* wrow = W_hh + (size_t)(q * 1024 + j0 + uu) * 1024
                                     + wk * 128 + s * 16;
            __half2 lo = __floats2half2_rn(wrow[2 * tg],     wrow[2 * tg + 1]);
            __half2 hi = __floats2half2_rn(wrow[8 + 2 * tg], wrow[8 + 2 * tg + 1]);
            bw[s][nt][0] = *(unsigned*)&lo;
            bw[s][nt][1] = *(unsigned*)&hi;
        }
    }

    float c_reg = c0[b * 1024 + j0 + u];
    float* out_cell = out + ((size_t)b * TSTEPS) * 1024 + j0 + u;

    // stage slot for our (b, u): fragment-packed local offset within kb block bid
    const int loc_u32  = ((b & 7) * 4 + ((u >> 1) & 3)) * 8
                       + ((((b >> 3) >> 1) << 2) | (((u >> 3) & 1) << 1) | ((b >> 3) & 1));
    const int loc_half = loc_u32 * 2 + (u & 1);

    // ---- prologue: stage h0 slice, coalesced publish, arrive ----
    stage[loc_half] = __float2half(h0[b * 1024 + j0 + u]);
    __syncthreads();
    if (wid == 0) {
        const uint4* sg = (const uint4*)stage;
        uint4* dst = (uint4*)(&g_hp[0][bid * 256]);
        dst[lane]      = sg[lane];
        dst[lane + 32] = sg[lane + 32];
        __syncwarp();
        if (lane == 0) bar_arrive(bid);
    }

    for (int t = 0; t < TSTEPS; ++t) {
        const unsigned* hb = g_hp[t & 1];

        // prefetch gate pre-activations (streaming; consumed after mma phase)
        float xpv[4];
        const float* xprow = &g_xp[(size_t)(t * 32 + b) * NGATE + j0 + u];
#pragma unroll
        for (int q = 0; q < 4; ++q) xpv[q] = __ldcs(xprow + q * 1024);

        // flat wait for epoch e0 + t + 1 (64 pollers)
        if (tid == 0) {
            const unsigned target = e0 + (unsigned)(t + 1);
            while ((int)(ldacq(&g_epoch) - target) < 0) { }
            __threadfence();
        }
        __syncthreads();

        // mma phase: warp (wk, wn): k16 blocks wk*8..+7, gate-rows wn*32..+32
        float C[8][4];
#pragma unroll
        for (int i = 0; i < 8; ++i) { C[i][0] = 0.f; C[i][1] = 0.f; C[i][2] = 0.f; C[i][3] = 0.f; }

#pragma unroll
        for (int s = 0; s < 8; ++s) {
            const unsigned* p = hb + ((wk * 8 + s) * 32 + lane) * 8;
            uint4 A0 = ldcg4(p);        // batches 0..15
            uint4 A1 = ldcg4(p + 4);    // batches 16..31
#pragma unroll
            for (int nt = 0; nt < 4; ++nt) {
                mma16(C[nt],     A0.x, A0.y, A0.z, A0.w, bw[s][nt][0], bw[s][nt][1]);
                mma16(C[4 + nt], A1.x, A1.y, A1.z, A1.w, bw[s][nt][0], bw[s][nt][1]);
            }
        }

        // K-split partials -> SMEM: red[(m*65 + r)*8 + wk]
#pragma unroll
        for (int mt = 0; mt < 2; ++mt) {
#pragma unroll
            for (int nt = 0; nt < 4; ++nt) {
                float* cc = C[mt * 4 + nt];
                int m  = mt * 16 + g;
                int r0 = wn * 32 + nt * 8 + tg * 2;
                red[((m)     * 65 + r0    ) * 8 + wk] = cc[0];
                red[((m)     * 65 + r0 + 1) * 8 + wk] = cc[1];
                red[((m + 8) * 65 + r0    ) * 8 + wk] = cc[2];
                red[((m + 8) * 65 + r0 + 1) * 8 + wk] = cc[3];
            }
        }
        __syncthreads();   // partials visible

        // gate math: one thread per (b, u)
        float z[4];
#pragma unroll
        for (int q = 0; q < 4; ++q) {
            int r = q * 16 + u;
            const float4* p = (const float4*)&red[(b * 65 + r) * 8];
            float4 s0 = p[0], s1 = p[1];
            z[q] = xpv[q] + (((s0.x + s0.y) + (s0.z + s0.w)) +
                             ((s1.x + s1.y) + (s1.z + s1.w)));
        }
        float iv = fsig(z[0]);
        float fv = fsig(z[1]);
        float gv = ftanh(z[2]);
        float ov = fsig(z[3]);
        c_reg = fv * c_reg + iv * gv;
        float hv = ov * ftanh(c_reg);

        if (t < TSTEPS - 1) {
            // stage h_{t+1} (fp16) -> coalesced 1KB publish by warp 0 -> arrive
            stage[loc_half] = __float2half(hv);
            __syncthreads();   // stage visible + red reuse safety
            if (wid == 0) {
                const uint4* sg = (const uint4*)stage;
                uint4* dst = (uint4*)(&g_hp[(t + 1) & 1][bid * 256]);
                dst[lane]      = sg[lane];
                dst[lane + 32] = sg[lane + 32];
                __syncwarp();
                if (lane == 0) bar_arrive(bid);
            }
            // streaming output store overlaps the next step's wait
            __stcs(out_cell + (size_t)t * 1024, hv);
        } else {
            __stcs(out_cell + (size_t)t * 1024, hv);
            if (out_size >= RES_ELEMS + 2 * BATCH * HID) {
                out[RES_ELEMS + b * 1024 + j0 + u]               = hv;     // hT
                out[RES_ELEMS + BATCH * HID + b * 1024 + j0 + u] = c_reg;  // cT
            }
        }
    }
}

// ---------------- launch ------------------------------------------------------
extern "C" void kernel_launch(void* const* d_in, const int* in_sizes, int n_in,
                              void* d_out, int out_size)
{
    const int*   tgt  = (const int*)  d_in[0];
    const float* h0   = (const float*)d_in[1];
    const float* c0   = (const float*)d_in[2];
    // d_in[3] encoder_outputs, d_in[4] src_lengths: unused by the reference
    const float* emb  = (const float*)d_in[5];
    const float* W_ih = (const float*)d_in[6];
    const float* W_hh = (const float*)d_in[7];
    const float* b_ih = (const float*)d_in[8];
    const float* b_hh = (const float*)d_in[9];
    float* out = (float*)d_out;

    const int lstm_smem = 16640 * 4 + 1024;   // red + stage = 67584 B
    cudaFuncSetAttribute(lstm_kernel, cudaFuncAttributeMaxDynamicSharedMemorySize,
                         lstm_smem);

    dim3 grid_x(32, 128);                 // (n blocks, m blocks)
    xproj_kernel<<<grid_x, 256>>>(tgt, emb, W_ih, b_ih, b_hh);

    lstm_kernel<<<NCTA, NTHR, lstm_smem>>>(h0, c0, W_hh, out, out_size);
}

// round 10
// speedup vs baseline: 1.4287x; 1.4287x over previous
#include <cuda_runtime.h>
#include <cuda_fp16.h>
#include <cstdint>

// Problem constants
#define BATCH   32
#define HID     1024
#define NGATE   4096          // 4*HID
#define TSTEPS  511           // T-1
#define MTOT    16352         // TSTEPS*BATCH
#define RES_ELEMS (511*32*1024)

// ---------------- device scratch (no runtime allocation allowed) -------------
__device__ float    g_xp[(size_t)MTOT * NGATE];    // x-projection (+bias), fp32
__device__ unsigned g_hp[2][64 * 32 * 8];          // h double-buffered, fp16 frag-packed
__device__ unsigned g_cnt1[8 * 32];                // level-1 arrival counters, 128B apart
__device__ unsigned g_cnt2;                        // level-2 counter
__device__ unsigned g_epoch;                       // released epoch (monotonic across replays)

// ---------------- small helpers ----------------------------------------------
__device__ __forceinline__ uint4 ldcg4(const unsigned* p) {
    uint4 v;
    asm volatile("ld.global.cg.v4.u32 {%0,%1,%2,%3}, [%4];"
                 : "=r"(v.x), "=r"(v.y), "=r"(v.z), "=r"(v.w) : "l"(p));
    return v;
}
__device__ __forceinline__ unsigned ldacq(const unsigned* p) {
    unsigned v;
    asm volatile("ld.acquire.gpu.global.u32 %0, [%1];" : "=r"(v) : "l"(p));
    return v;
}
// fp16 mma (both kernels)
__device__ __forceinline__ void mma16(float c[4], unsigned a0, unsigned a1, unsigned a2,
                                      unsigned a3, unsigned b0, unsigned b1) {
    asm volatile(
        "mma.sync.aligned.m16n8k16.row.col.f32.f16.f16.f32 "
        "{%0,%1,%2,%3}, {%4,%5,%6,%7}, {%8,%9}, {%0,%1,%2,%3};"
        : "+f"(c[0]), "+f"(c[1]), "+f"(c[2]), "+f"(c[3])
        : "r"(a0), "r"(a1), "r"(a2), "r"(a3), "r"(b0), "r"(b1));
}
__device__ __forceinline__ unsigned pack_h2(float x, float y) {
    __half2 h = __floats2half2_rn(x, y);
    return *(unsigned*)&h;
}
__device__ __forceinline__ float fsig(float x) {
    return __fdividef(1.f, 1.f + __expf(-x));
}
__device__ __forceinline__ float ftanh(float x) {
    return __fmaf_rn(2.f, fsig(2.f * x), -1.f);
}
// fp16 fragment-pack u32-slot index for h element (b, k); (k&1) selects the half.
__device__ __forceinline__ int hp16_index(int b, int k) {
    int kb   = k >> 4;
    int d    = (k >> 3) & 1;
    int tg   = (k >> 1) & 3;
    int g    = b & 7;
    int q    = b >> 3;
    int slot = ((q >> 1) << 2) | (d << 1) | (q & 1);
    int ln   = g * 4 + tg;
    return (kb * 32 + ln) * 8 + slot;
}

// arrival fan-in tree (R6: 8 counters x16 CTAs -> cnt2 x8 -> epoch).
// epoch bumps ONLY after all 128 arrivals => e0 snapshot at kernel start is safe.
__device__ __forceinline__ void bar_arrive(int bid) {
    __threadfence();
    unsigned o1 = atomicAdd(&g_cnt1[(bid & 7) * 32], 1u);
    if ((o1 & 15u) == 15u) {
        unsigned o2 = atomicAdd(&g_cnt2, 1u);
        if ((o2 & 7u) == 7u) atomicAdd(&g_epoch, 1u);
    }
}

// ---------------- x_proj: xp[t*32+b][g] = emb[tgt[b][t]] . W_ih[g] + bias ----
// fp16 m16n8k16 GEMM, BM=128, BN=256, BK=32. 256 threads, warp grid 2(m)x4(n),
// each warp covers 64 output cols. SMEM fp16-packed with 16-slot rotation:
// phys_k2 = (k2 + 2*(row&7)) & 15 -> conflict-free fragment fetch.
__global__ void __launch_bounds__(256)
xproj_kernel(const int* __restrict__ tgt, const float* __restrict__ emb,
             const float* __restrict__ W, const float* __restrict__ b_ih,
             const float* __restrict__ b_hh)
{
    __shared__ unsigned As[128 * 16];   // 8 KB : A tile, fp16 pairs
    __shared__ unsigned Bs[256 * 16];   // 16 KB: B tile (W_ih rows), fp16 pairs

    const int nb = blockIdx.x, mb = blockIdx.y;
    const int tid = threadIdx.x, lane = tid & 31, wid = tid >> 5;
    const int warp_m = wid & 1, warp_n = wid >> 1;
    const int c4 = tid & 7, row0 = tid >> 3;   // loader: 8 col-chunks x 32 rows
    const int g = lane >> 2, tg = lane & 3;

    // tokens for this thread's 4 A rows (fixed over the k loop)
    int toks[4];
#pragma unroll
    for (int r = 0; r < 4; ++r) {
        int m  = row0 + r * 32;
        int mg = mb * 128 + m;              // global m = t*32 + b
        int bb = mg & 31, tt = mg >> 5;
        int tok = tgt[bb * 512 + tt];
        toks[r] = (tok < 0 || tok > 31999) ? 0 : tok;
    }

    float acc[4][8][4];
#pragma unroll
    for (int mt = 0; mt < 4; ++mt)
#pragma unroll
        for (int nt = 0; nt < 8; ++nt)
#pragma unroll
            for (int i = 0; i < 4; ++i) acc[mt][nt][i] = 0.f;

    for (int kt = 0; kt < 32; ++kt) {
        const int koff = kt * 32 + c4 * 4;
        // A tile: 128 rows (4 per thread)
#pragma unroll
        for (int r = 0; r < 4; ++r) {
            int m = row0 + r * 32;
            float4 va = *(const float4*)(emb + (size_t)toks[r] * 1024 + koff);
            int phys = 2 * ((c4 + m) & 7);
            As[m * 16 + phys]     = pack_h2(va.x, va.y);
            As[m * 16 + phys + 1] = pack_h2(va.z, va.w);
        }
        // B tile: 256 rows (8 per thread)
#pragma unroll
        for (int r = 0; r < 8; ++r) {
            int m = row0 + r * 32;
            float4 vb = *(const float4*)(W + (size_t)(nb * 256 + m) * 1024 + koff);
            int phys = 2 * ((c4 + m) & 7);
            Bs[m * 16 + phys]     = pack_h2(vb.x, vb.y);
            Bs[m * 16 + phys + 1] = pack_h2(vb.z, vb.w);
        }
        __syncthreads();

#pragma unroll
        for (int ks = 0; ks < 2; ++ks) {
            const int kb2 = ks * 8;
            unsigned a[4][4], bf[8][2];
#pragma unroll
            for (int mt = 0; mt < 4; ++mt) {
                int m   = warp_m * 64 + mt * 16 + g;
                int rot = 2 * (m & 7);
                a[mt][0] = As[m * 16       + ((kb2 + tg     + rot) & 15)];
                a[mt][1] = As[(m + 8) * 16 + ((kb2 + tg     + rot) & 15)];
                a[mt][2] = As[m * 16       + ((kb2 + tg + 4 + rot) & 15)];
                a[mt][3] = As[(m + 8) * 16 + ((kb2 + tg + 4 + rot) & 15)];
            }
#pragma unroll
            for (int nt = 0; nt < 8; ++nt) {
                int n   = warp_n * 64 + nt * 8 + g;
                int rot = 2 * (n & 7);
                bf[nt][0] = Bs[n * 16 + ((kb2 + tg     + rot) & 15)];
                bf[nt][1] = Bs[n * 16 + ((kb2 + tg + 4 + rot) & 15)];
            }
#pragma unroll
            for (int mt = 0; mt < 4; ++mt)
#pragma unroll
                for (int nt = 0; nt < 8; ++nt)
                    mma16(acc[mt][nt], a[mt][0], a[mt][1], a[mt][2], a[mt][3],
                          bf[nt][0], bf[nt][1]);
        }
        __syncthreads();
    }

    // epilogue: add bias, write g_xp, mask m tail (MTOT = 16352)
#pragma unroll
    for (int mt = 0; mt < 4; ++mt) {
#pragma unroll
        for (int nt = 0; nt < 8; ++nt) {
            int m0 = mb * 128 + warp_m * 64 + mt * 16 + g;
            int n0 = nb * 256 + warp_n * 64 + nt * 8 + tg * 2;
            float bia0 = b_ih[n0] + b_hh[n0];
            float bia1 = b_ih[n0 + 1] + b_hh[n0 + 1];
            if (m0 < MTOT) {
                g_xp[(size_t)m0 * NGATE + n0]     = acc[mt][nt][0] + bia0;
                g_xp[(size_t)m0 * NGATE + n0 + 1] = acc[mt][nt][1] + bia1;
            }
            if (m0 + 8 < MTOT) {
                g_xp[(size_t)(m0 + 8) * NGATE + n0]     = acc[mt][nt][2] + bia0;
                g_xp[(size_t)(m0 + 8) * NGATE + n0 + 1] = acc[mt][nt][3] + bia1;
            }
        }
    }
}

// ---------------- persistent recurrent kernel (R6 verbatim — measured best) --
// 128 CTAs x 256 threads. CTA c owns hidden units [c*8, c*8+8).
// fp16 m16n8k16 mma, W_hh fragments in registers, h broadcast fp16 frag-packed.
// Per-step sync: tree arrivals (8 spread counters -> cnt2 -> epoch), flat
// acquire-poll of g_epoch by tid0 of each CTA.
__global__ void __launch_bounds__(256, 1)
lstm_kernel(const float* __restrict__ h0, const float* __restrict__ c0,
            const float* __restrict__ W_hh, float* __restrict__ out, int out_size)
{
    __shared__ float red[8448];   // idx(m,n,w) = (m*33+n)*8+w

    const int tid = threadIdx.x, lane = tid & 31, wid = tid >> 5;
    const int g = lane >> 2, tg = lane & 3;
    const int j0 = blockIdx.x * 8;
    const int b = tid >> 3, jj = tid & 7;           // this thread's cell (b, j0+jj)

    const unsigned e0 = g_epoch;                    // stable at kernel start

    // ---- load this CTA's W_hh fragments into registers (fp16 pairs) ----
    unsigned bw[8][4][2];
#pragma unroll
    for (int s = 0; s < 8; ++s) {
#pragma unroll
        for (int nt = 0; nt < 4; ++nt) {
            int r = nt * 8 + g;                 // local gate-row 0..31
            int q = r >> 3, jr = r & 7;
            const float* wrow = W_hh + (size_t)(q * 1024 + j0 + jr) * 1024
                                     + wid * 128 + s * 16;
            bw[s][nt][0] = pack_h2(wrow[2 * tg],     wrow[2 * tg + 1]);
            bw[s][nt][1] = pack_h2(wrow[8 + 2 * tg], wrow[8 + 2 * tg + 1]);
        }
    }

    float c_reg = c0[b * 1024 + j0 + jj];
    float* out_cell = out + ((size_t)b * TSTEPS) * 1024 + j0 + jj;

    // own h slot (u32 index + half offset)
    const int hk      = j0 + jj;
    const int hp_idx  = hp16_index(b, hk);
    const int hp_half = hk & 1;

    // ---- prologue: pack own h0 slice (fp16), arrive ----
    {
        __half hv = __float2half(h0[b * 1024 + hk]);
        *(__half*)((char*)&g_hp[0][hp_idx] + hp_half * 2) = hv;
    }
    __syncthreads();
    if (tid == 0) bar_arrive(blockIdx.x);

    for (int t = 0; t < TSTEPS; ++t) {
        const unsigned* hb = g_hp[t & 1];

        // prefetch gate pre-activations (streaming; consumed after mma phase)
        float xpv[4];
        const float* xprow = &g_xp[(size_t)(t * 32 + b) * NGATE + j0 + jj];
#pragma unroll
        for (int q = 0; q < 4; ++q) xpv[q] = __ldcs(xprow + q * 1024);

        // wait for epoch e0 + t + 1 (all CTAs published h_t)
        if (tid == 0) {
            const unsigned target = e0 + (unsigned)(t + 1);
            while ((int)(ldacq(&g_epoch) - target) < 0) { }
            __threadfence();
        }
        __syncthreads();

        // mma phase: warp wid owns k16 blocks wid*8 .. wid*8+7
        float C[8][4];
#pragma unroll
        for (int i = 0; i < 8; ++i) { C[i][0] = 0.f; C[i][1] = 0.f; C[i][2] = 0.f; C[i][3] = 0.f; }

#pragma unroll
        for (int s = 0; s < 8; ++s) {
            const unsigned* p = hb + ((wid * 8 + s) * 32 + lane) * 8;
            uint4 A0 = ldcg4(p);        // batches 0..15
            uint4 A1 = ldcg4(p + 4);    // batches 16..31
#pragma unroll
            for (int nt = 0; nt < 4; ++nt) {
                mma16(C[nt],     A0.x, A0.y, A0.z, A0.w, bw[s][nt][0], bw[s][nt][1]);
                mma16(C[4 + nt], A1.x, A1.y, A1.z, A1.w, bw[s][nt][0], bw[s][nt][1]);
            }
        }

        // K-split partials -> SMEM
#pragma unroll
        for (int mt = 0; mt < 2; ++mt) {
#pragma unroll
            for (int nt = 0; nt < 4; ++nt) {
                float* cc = C[mt * 4 + nt];
                int m  = mt * 16 + g;
                int n0 = nt * 8 + tg * 2;
                red[((m)     * 33 + n0    ) * 8 + wid] = cc[0];
                red[((m)     * 33 + n0 + 1) * 8 + wid] = cc[1];
                red[((m + 8) * 33 + n0    ) * 8 + wid] = cc[2];
                red[((m + 8) * 33 + n0 + 1) * 8 + wid] = cc[3];
            }
        }
        __syncthreads();   // partials visible

        // gate math: one thread per (b, jj)
        float z[4];
#pragma unroll
        for (int q = 0; q < 4; ++q) {
            int r = q * 8 + jj;
            const float4* p = (const float4*)&red[(b * 33 + r) * 8];
            float4 s0 = p[0], s1 = p[1];
            z[q] = xpv[q] + (((s0.x + s0.y) + (s0.z + s0.w)) +
                             ((s1.x + s1.y) + (s1.z + s1.w)));
        }
        float iv = fsig(z[0]);
        float fv = fsig(z[1]);
        float gv = ftanh(z[2]);
        float ov = fsig(z[3]);
        c_reg = fv * c_reg + iv * gv;
        float hv = ov * ftanh(c_reg);

        if (t < TSTEPS - 1) {
            // publish packed h_{t+1} FIRST (critical path), then arrive
            __half hh = __float2half(hv);
            *(__half*)((char*)&g_hp[(t + 1) & 1][hp_idx] + hp_half * 2) = hh;
            __syncthreads();   // h stores done + red reuse safety
            if (tid == 0) bar_arrive(blockIdx.x);
            // streaming output store overlaps the next step's wait
            __stcs(out_cell + (size_t)t * 1024, hv);
        } else {
            __stcs(out_cell + (size_t)t * 1024, hv);
            if (out_size >= RES_ELEMS + 2 * BATCH * HID) {
                out[RES_ELEMS + b * 1024 + j0 + jj]               = hv;     // hT
                out[RES_ELEMS + BATCH * HID + b * 1024 + j0 + jj] = c_reg;  // cT
            }
        }
    }
}

// ---------------- launch ------------------------------------------------------
extern "C" void kernel_launch(void* const* d_in, const int* in_sizes, int n_in,
                              void* d_out, int out_size)
{
    const int*   tgt  = (const int*)  d_in[0];
    const float* h0   = (const float*)d_in[1];
    const float* c0   = (const float*)d_in[2];
    // d_in[3] encoder_outputs, d_in[4] src_lengths: unused by the reference
    const float* emb  = (const float*)d_in[5];
    const float* W_ih = (const float*)d_in[6];
    const float* W_hh = (const float*)d_in[7];
    const float* b_ih = (const float*)d_in[8];
    const float* b_hh = (const float*)d_in[9];
    float* out = (float*)d_out;

    dim3 grid_x(16, 128);                 // (n blocks of 256, m blocks of 128)
    xproj_kernel<<<grid_x, 256>>>(tgt, emb, W_ih, b_ih, b_hh);

    lstm_kernel<<<128, 256>>>(h0, c0, W_hh, out, out_size);
}

// round 11
// speedup vs baseline: 1.5385x; 1.0769x over previous
#include <cuda_runtime.h>
#include <cuda_fp16.h>
#include <cstdint>

// Problem constants
#define BATCH   32
#define HID     1024
#define NGATE   4096          // 4*HID
#define TSTEPS  511           // T-1
#define MTOT    16352         // TSTEPS*BATCH
#define RES_ELEMS (511*32*1024)

// ---------------- device scratch (no runtime allocation allowed) -------------
__device__ float    g_xp[(size_t)MTOT * NGATE];    // x-projection (+bias), fp32
__device__ unsigned g_hp[2][64 * 32 * 8];          // h double-buffered, fp16 frag-packed
__device__ unsigned g_cnt;                         // single barrier counter (reset by xproj)

// ---------------- small helpers ----------------------------------------------
__device__ __forceinline__ uint4 ldcg4(const unsigned* p) {
    uint4 v;
    asm volatile("ld.global.cg.v4.u32 {%0,%1,%2,%3}, [%4];"
                 : "=r"(v.x), "=r"(v.y), "=r"(v.z), "=r"(v.w) : "l"(p));
    return v;
}
__device__ __forceinline__ unsigned ldacq(const unsigned* p) {
    unsigned v;
    asm volatile("ld.acquire.gpu.global.u32 %0, [%1];" : "=r"(v) : "l"(p));
    return v;
}
// fp16 mma (both kernels)
__device__ __forceinline__ void mma16(float c[4], unsigned a0, unsigned a1, unsigned a2,
                                      unsigned a3, unsigned b0, unsigned b1) {
    asm volatile(
        "mma.sync.aligned.m16n8k16.row.col.f32.f16.f16.f32 "
        "{%0,%1,%2,%3}, {%4,%5,%6,%7}, {%8,%9}, {%0,%1,%2,%3};"
        : "+f"(c[0]), "+f"(c[1]), "+f"(c[2]), "+f"(c[3])
        : "r"(a0), "r"(a1), "r"(a2), "r"(a3), "r"(b0), "r"(b1));
}
__device__ __forceinline__ unsigned pack_h2(float x, float y) {
    __half2 h = __floats2half2_rn(x, y);
    return *(unsigned*)&h;
}
__device__ __forceinline__ float fsig(float x) {
    return __fdividef(1.f, 1.f + __expf(-x));
}
__device__ __forceinline__ float ftanh(float x) {
    return __fmaf_rn(2.f, fsig(2.f * x), -1.f);
}
// fp16 fragment-pack u32-slot index for h element (b, k); (k&1) selects the half.
__device__ __forceinline__ int hp16_index(int b, int k) {
    int kb   = k >> 4;
    int d    = (k >> 3) & 1;
    int tg   = (k >> 1) & 3;
    int g    = b & 7;
    int q    = b >> 3;
    int slot = ((q >> 1) << 2) | (d << 1) | (q & 1);
    int ln   = g * 4 + tg;
    return (kb * 32 + ln) * 8 + slot;
}

// ---------------- x_proj: xp[t*32+b][g] = emb[tgt[b][t]] . W_ih[g] + bias ----
// fp16 m16n8k16 GEMM, BM=128, BN=256, BK=32. Also resets the lstm barrier
// counter (stream order guarantees completion before lstm starts).
__global__ void __launch_bounds__(256)
xproj_kernel(const int* __restrict__ tgt, const float* __restrict__ emb,
             const float* __restrict__ W, const float* __restrict__ b_ih,
             const float* __restrict__ b_hh)
{
    __shared__ unsigned As[128 * 16];   // 8 KB : A tile, fp16 pairs
    __shared__ unsigned Bs[256 * 16];   // 16 KB: B tile (W_ih rows), fp16 pairs

    if (blockIdx.x == 0 && blockIdx.y == 0 && threadIdx.x == 0)
        g_cnt = 0u;                     // reset lstm barrier counter each launch

    const int nb = blockIdx.x, mb = blockIdx.y;
    const int tid = threadIdx.x, lane = tid & 31, wid = tid >> 5;
    const int warp_m = wid & 1, warp_n = wid >> 1;
    const int c4 = tid & 7, row0 = tid >> 3;   // loader: 8 col-chunks x 32 rows
    const int g = lane >> 2, tg = lane & 3;

    // tokens for this thread's 4 A rows (fixed over the k loop)
    int toks[4];
#pragma unroll
    for (int r = 0; r < 4; ++r) {
        int m  = row0 + r * 32;
        int mg = mb * 128 + m;              // global m = t*32 + b
        int bb = mg & 31, tt = mg >> 5;
        int tok = tgt[bb * 512 + tt];
        toks[r] = (tok < 0 || tok > 31999) ? 0 : tok;
    }

    float acc[4][8][4];
#pragma unroll
    for (int mt = 0; mt < 4; ++mt)
#pragma unroll
        for (int nt = 0; nt < 8; ++nt)
#pragma unroll
            for (int i = 0; i < 4; ++i) acc[mt][nt][i] = 0.f;

    for (int kt = 0; kt < 32; ++kt) {
        const int koff = kt * 32 + c4 * 4;
        // A tile: 128 rows (4 per thread)
#pragma unroll
        for (int r = 0; r < 4; ++r) {
            int m = row0 + r * 32;
            float4 va = *(const float4*)(emb + (size_t)toks[r] * 1024 + koff);
            int phys = 2 * ((c4 + m) & 7);
            As[m * 16 + phys]     = pack_h2(va.x, va.y);
            As[m * 16 + phys + 1] = pack_h2(va.z, va.w);
        }
        // B tile: 256 rows (8 per thread)
#pragma unroll
        for (int r = 0; r < 8; ++r) {
            int m = row0 + r * 32;
            float4 vb = *(const float4*)(W + (size_t)(nb * 256 + m) * 1024 + koff);
            int phys = 2 * ((c4 + m) & 7);
            Bs[m * 16 + phys]     = pack_h2(vb.x, vb.y);
            Bs[m * 16 + phys + 1] = pack_h2(vb.z, vb.w);
        }
        __syncthreads();

#pragma unroll
        for (int ks = 0; ks < 2; ++ks) {
            const int kb2 = ks * 8;
            unsigned a[4][4], bf[8][2];
#pragma unroll
            for (int mt = 0; mt < 4; ++mt) {
                int m   = warp_m * 64 + mt * 16 + g;
                int rot = 2 * (m & 7);
                a[mt][0] = As[m * 16       + ((kb2 + tg     + rot) & 15)];
                a[mt][1] = As[(m + 8) * 16 + ((kb2 + tg     + rot) & 15)];
                a[mt][2] = As[m * 16       + ((kb2 + tg + 4 + rot) & 15)];
                a[mt][3] = As[(m + 8) * 16 + ((kb2 + tg + 4 + rot) & 15)];
            }
#pragma unroll
            for (int nt = 0; nt < 8; ++nt) {
                int n   = warp_n * 64 + nt * 8 + g;
                int rot = 2 * (n & 7);
                bf[nt][0] = Bs[n * 16 + ((kb2 + tg     + rot) & 15)];
                bf[nt][1] = Bs[n * 16 + ((kb2 + tg + 4 + rot) & 15)];
            }
#pragma unroll
            for (int mt = 0; mt < 4; ++mt)
#pragma unroll
                for (int nt = 0; nt < 8; ++nt)
                    mma16(acc[mt][nt], a[mt][0], a[mt][1], a[mt][2], a[mt][3],
                          bf[nt][0], bf[nt][1]);
        }
        __syncthreads();
    }

    // epilogue: add bias, write g_xp, mask m tail (MTOT = 16352)
#pragma unroll
    for (int mt = 0; mt < 4; ++mt) {
#pragma unroll
        for (int nt = 0; nt < 8; ++nt) {
            int m0 = mb * 128 + warp_m * 64 + mt * 16 + g;
            int n0 = nb * 256 + warp_n * 64 + nt * 8 + tg * 2;
            float bia0 = b_ih[n0] + b_hh[n0];
            float bia1 = b_ih[n0 + 1] + b_hh[n0 + 1];
            if (m0 < MTOT) {
                g_xp[(size_t)m0 * NGATE + n0]     = acc[mt][nt][0] + bia0;
                g_xp[(size_t)m0 * NGATE + n0 + 1] = acc[mt][nt][1] + bia1;
            }
            if (m0 + 8 < MTOT) {
                g_xp[(size_t)(m0 + 8) * NGATE + n0]     = acc[mt][nt][2] + bia0;
                g_xp[(size_t)(m0 + 8) * NGATE + n0 + 1] = acc[mt][nt][3] + bia1;
            }
        }
    }
}

// ---------------- persistent recurrent kernel --------------------------------
// 128 CTAs x 256 threads (R10 structure). CTA c owns hidden units [c*8, c*8+8).
// fp16 m16n8k16 mma, W_hh fragments in registers, h broadcast fp16 frag-packed.
// Per-step sync: SINGLE-COUNTER barrier. Arrival = threadfence + RED.E.ADD
// (atomicAdd with unused result -> fire-and-forget, no dependent chain).
// Detection = tid0 acquire-polls the counter for 128*(t+1). The 128th RED *is*
// the release -- no separate epoch hop. Counter reset by xproj each launch.
__global__ void __launch_bounds__(256, 1)
lstm_kernel(const float* __restrict__ h0, const float* __restrict__ c0,
            const float* __restrict__ W_hh, float* __restrict__ out, int out_size)
{
    __shared__ float red[8448];   // idx(m,n,w) = (m*33+n)*8+w

    const int tid = threadIdx.x, lane = tid & 31, wid = tid >> 5;
    const int g = lane >> 2, tg = lane & 3;
    const int j0 = blockIdx.x * 8;
    const int b = tid >> 3, jj = tid & 7;           // this thread's cell (b, j0+jj)

    // ---- load this CTA's W_hh fragments into registers (fp16 pairs) ----
    unsigned bw[8][4][2];
#pragma unroll
    for (int s = 0; s < 8; ++s) {
#pragma unroll
        for (int nt = 0; nt < 4; ++nt) {
            int r = nt * 8 + g;                 // local gate-row 0..31
            int q = r >> 3, jr = r & 7;
            const float* wrow = W_hh + (size_t)(q * 1024 + j0 + jr) * 1024
                                     + wid * 128 + s * 16;
            bw[s][nt][0] = pack_h2(wrow[2 * tg],     wrow[2 * tg + 1]);
            bw[s][nt][1] = pack_h2(wrow[8 + 2 * tg], wrow[8 + 2 * tg + 1]);
        }
    }

    float c_reg = c0[b * 1024 + j0 + jj];
    float* out_cell = out + ((size_t)b * TSTEPS) * 1024 + j0 + jj;

    // own h u32 slot (paired: jj even thread stores both halves for jj, jj+1)
    const int hk     = j0 + jj;
    const int hp_idx = hp16_index(b, hk);

    // ---- prologue: pack own h0 slice (paired 4B stores), arrive ----
    {
        __half hh = __float2half(h0[b * 1024 + hk]);
        unsigned hu = (unsigned)__half_as_ushort(hh);
        unsigned up = __shfl_down_sync(0xffffffffu, hu, 1);
        if ((jj & 1) == 0) g_hp[0][hp_idx] = hu | (up << 16);
    }
    __syncthreads();
    if (tid == 0) {
        __threadfence();
        atomicAdd(&g_cnt, 1u);      // result unused -> RED.E.ADD
    }

    for (int t = 0; t < TSTEPS; ++t) {
        const unsigned* hb = g_hp[t & 1];

        // prefetch gate pre-activations (streaming; consumed after mma phase)
        float xpv[4];
        const float* xprow = &g_xp[(size_t)(t * 32 + b) * NGATE + j0 + jj];
#pragma unroll
        for (int q = 0; q < 4; ++q) xpv[q] = __ldcs(xprow + q * 1024);

        // wait until all 128 CTAs have published h_t: counter >= 128*(t+1)
        if (tid == 0) {
            const unsigned target = 128u * (unsigned)(t + 1);
            while ((int)(ldacq(&g_cnt) - target) < 0) { }
            __threadfence();
        }
        __syncthreads();

        // mma phase: warp wid owns k16 blocks wid*8 .. wid*8+7
        float C[8][4];
#pragma unroll
        for (int i = 0; i < 8; ++i) { C[i][0] = 0.f; C[i][1] = 0.f; C[i][2] = 0.f; C[i][3] = 0.f; }

#pragma unroll
        for (int s = 0; s < 8; ++s) {
            const unsigned* p = hb + ((wid * 8 + s) * 32 + lane) * 8;
            uint4 A0 = ldcg4(p);        // batches 0..15
            uint4 A1 = ldcg4(p + 4);    // batches 16..31
#pragma unroll
            for (int nt = 0; nt < 4; ++nt) {
                mma16(C[nt],     A0.x, A0.y, A0.z, A0.w, bw[s][nt][0], bw[s][nt][1]);
                mma16(C[4 + nt], A1.x, A1.y, A1.z, A1.w, bw[s][nt][0], bw[s][nt][1]);
            }
        }

        // K-split partials -> SMEM
#pragma unroll
        for (int mt = 0; mt < 2; ++mt) {
#pragma unroll
            for (int nt = 0; nt < 4; ++nt) {
                float* cc = C[mt * 4 + nt];
                int m  = mt * 16 + g;
                int n0 = nt * 8 + tg * 2;
                red[((m)     * 33 + n0    ) * 8 + wid] = cc[0];
                red[((m)     * 33 + n0 + 1) * 8 + wid] = cc[1];
                red[((m + 8) * 33 + n0    ) * 8 + wid] = cc[2];
                red[((m + 8) * 33 + n0 + 1) * 8 + wid] = cc[3];
            }
        }
        __syncthreads();   // partials visible

        // gate math: one thread per (b, jj)
        float z[4];
#pragma unroll
        for (int q = 0; q < 4; ++q) {
            int r = q * 8 + jj;
            const float4* p = (const float4*)&red[(b * 33 + r) * 8];
            float4 s0 = p[0], s1 = p[1];
            z[q] = xpv[q] + (((s0.x + s0.y) + (s0.z + s0.w)) +
                             ((s1.x + s1.y) + (s1.z + s1.w)));
        }
        float iv = fsig(z[0]);
        float fv = fsig(z[1]);
        float gv = ftanh(z[2]);
        float ov = fsig(z[3]);
        c_reg = fv * c_reg + iv * gv;
        float hv = ov * ftanh(c_reg);

        if (t < TSTEPS - 1) {
            // publish packed h_{t+1} (paired 4B stores) FIRST, then arrive
            __half hh = __float2half(hv);
            unsigned hu = (unsigned)__half_as_ushort(hh);
            unsigned up = __shfl_down_sync(0xffffffffu, hu, 1);
            if ((jj & 1) == 0) g_hp[(t + 1) & 1][hp_idx] = hu | (up << 16);
            __syncthreads();   // h stores done + red reuse safety
            if (tid == 0) {
                __threadfence();
                atomicAdd(&g_cnt, 1u);   // RED.E.ADD
            }
            // streaming output store overlaps the next step's wait
            __stcs(out_cell + (size_t)t * 1024, hv);
        } else {
            __stcs(out_cell + (size_t)t * 1024, hv);
            if (out_size >= RES_ELEMS + 2 * BATCH * HID) {
                out[RES_ELEMS + b * 1024 + j0 + jj]               = hv;     // hT
                out[RES_ELEMS + BATCH * HID + b * 1024 + j0 + jj] = c_reg;  // cT
            }
        }
    }
}

// ---------------- launch ------------------------------------------------------
extern "C" void kernel_launch(void* const* d_in, const int* in_sizes, int n_in,
                              void* d_out, int out_size)
{
    const int*   tgt  = (const int*)  d_in[0];
    const float* h0   = (const float*)d_in[1];
    const float* c0   = (const float*)d_in[2];
    // d_in[3] encoder_outputs, d_in[4] src_lengths: unused by the reference
    const float* emb  = (const float*)d_in[5];
    const float* W_ih = (const float*)d_in[6];
    const float* W_hh = (const float*)d_in[7];
    const float* b_ih = (const float*)d_in[8];
    const float* b_hh = (const float*)d_in[9];
    float* out = (float*)d_out;

    dim3 grid_x(16, 128);                 // (n blocks of 256, m blocks of 128)
    xproj_kernel<<<grid_x, 256>>>(tgt, emb, W_ih, b_ih, b_hh);

    lstm_kernel<<<128, 256>>>(h0, c0, W_hh, out, out_size);
}

// round 13
// speedup vs baseline: 1.7506x; 1.1378x over previous
#include <cuda_runtime.h>
#include <cuda_fp16.h>
#include <cstdint>

// Problem constants
#define BATCH   32
#define HID     1024
#define NGATE   4096          // 4*HID
#define TSTEPS  511           // T-1
#define MTOT    16352         // TSTEPS*BATCH
#define RES_ELEMS (511*32*1024)

// ---------------- device scratch (no runtime allocation allowed) -------------
__device__ float    g_xp[(size_t)MTOT * NGATE];    // x-projection (+bias), fp32
__device__ unsigned g_hp[2][64 * 32 * 8];          // h double-buffered, fp16 frag-packed
__device__ unsigned g_cnt;                         // single barrier counter (reset by xproj)

// ---------------- small helpers ----------------------------------------------
__device__ __forceinline__ uint4 ldcg4(const unsigned* p) {
    uint4 v;
    asm volatile("ld.global.cg.v4.u32 {%0,%1,%2,%3}, [%4];"
                 : "=r"(v.x), "=r"(v.y), "=r"(v.z), "=r"(v.w) : "l"(p));
    return v;
}
__device__ __forceinline__ unsigned ldacq(const unsigned* p) {
    unsigned v;
    asm volatile("ld.acquire.gpu.global.u32 %0, [%1];" : "=r"(v) : "l"(p));
    return v;
}
// fire-and-forget release reduction: folds the publish fence into the atomic
__device__ __forceinline__ void red_release_add(unsigned* p, unsigned v) {
    asm volatile("red.release.gpu.global.add.u32 [%0], %1;" :: "l"(p), "r"(v) : "memory");
}
// fp16 mma (both kernels)
__device__ __forceinline__ void mma16(float c[4], unsigned a0, unsigned a1, unsigned a2,
                                      unsigned a3, unsigned b0, unsigned b1) {
    asm volatile(
        "mma.sync.aligned.m16n8k16.row.col.f32.f16.f16.f32 "
        "{%0,%1,%2,%3}, {%4,%5,%6,%7}, {%8,%9}, {%0,%1,%2,%3};"
        : "+f"(c[0]), "+f"(c[1]), "+f"(c[2]), "+f"(c[3])
        : "r"(a0), "r"(a1), "r"(a2), "r"(a3), "r"(b0), "r"(b1));
}
__device__ __forceinline__ unsigned pack_h2(float x, float y) {
    __half2 h = __floats2half2_rn(x, y);
    return *(unsigned*)&h;
}
__device__ __forceinline__ float fsig(float x) {
    return __fdividef(1.f, 1.f + __expf(-x));
}
__device__ __forceinline__ float ftanh(float x) {
    return __fmaf_rn(2.f, fsig(2.f * x), -1.f);
}
// fp16 fragment-pack u32-slot index for h element (b, k); (k&1) selects the half.
__device__ __forceinline__ int hp16_index(int b, int k) {
    int kb   = k >> 4;
    int d    = (k >> 3) & 1;
    int tg   = (k >> 1) & 3;
    int g    = b & 7;
    int q    = b >> 3;
    int slot = ((q >> 1) << 2) | (d << 1) | (q & 1);
    int ln   = g * 4 + tg;
    return (kb * 32 + ln) * 8 + slot;
}

// ---------------- x_proj: xp[t*32+b][g] = emb[tgt[b][t]] . W_ih[g] + bias ----
// fp16 m16n8k16 GEMM, BM=64, BN=256, BK=32, 2 CTAs/SM (occupancy for latency
// hiding). Warp grid 2(m)x4(n): warp covers 32 rows x 64 cols.
// Also resets the lstm barrier counter (stream order).
__global__ void __launch_bounds__(256, 2)
xproj_kernel(const int* __restrict__ tgt, const float* __restrict__ emb,
             const float* __restrict__ W, const float* __restrict__ b_ih,
             const float* __restrict__ b_hh)
{
    __shared__ unsigned As[64 * 16];    // 4 KB : A tile, fp16 pairs
    __shared__ unsigned Bs[256 * 16];   // 16 KB: B tile (W_ih rows), fp16 pairs

    if (blockIdx.x == 0 && blockIdx.y == 0 && threadIdx.x == 0)
        g_cnt = 0u;                     // reset lstm barrier counter each launch

    const int nb = blockIdx.x, mb = blockIdx.y;
    const int tid = threadIdx.x, lane = tid & 31, wid = tid >> 5;
    const int warp_m = wid & 1, warp_n = wid >> 1;
    const int c4 = tid & 7, row0 = tid >> 3;   // loader: 8 col-chunks x 32 rows
    const int g = lane >> 2, tg = lane & 3;

    // tokens for this thread's 2 A rows (fixed over the k loop)
    int toks[2];
#pragma unroll
    for (int r = 0; r < 2; ++r) {
        int m  = row0 + r * 32;
        int mg = mb * 64 + m;               // global m = t*32 + b
        int bb = mg & 31, tt = mg >> 5;
        int tok = tgt[bb * 512 + tt];
        toks[r] = (tok < 0 || tok > 31999) ? 0 : tok;
    }

    float acc[2][8][4];
#pragma unroll
    for (int mt = 0; mt < 2; ++mt)
#pragma unroll
        for (int nt = 0; nt < 8; ++nt)
#pragma unroll
            for (int i = 0; i < 4; ++i) acc[mt][nt][i] = 0.f;

    for (int kt = 0; kt < 32; ++kt) {
        const int koff = kt * 32 + c4 * 4;
        // A tile: 64 rows (2 per thread)
#pragma unroll
        for (int r = 0; r < 2; ++r) {
            int m = row0 + r * 32;
            float4 va = *(const float4*)(emb + (size_t)toks[r] * 1024 + koff);
            int phys = 2 * ((c4 + m) & 7);
            As[m * 16 + phys]     = pack_h2(va.x, va.y);
            As[m * 16 + phys + 1] = pack_h2(va.z, va.w);
        }
        // B tile: 256 rows (8 per thread)
#pragma unroll
        for (int r = 0; r < 8; ++r) {
            int m = row0 + r * 32;
            float4 vb = *(const float4*)(W + (size_t)(nb * 256 + m) * 1024 + koff);
            int phys = 2 * ((c4 + m) & 7);
            Bs[m * 16 + phys]     = pack_h2(vb.x, vb.y);
            Bs[m * 16 + phys + 1] = pack_h2(vb.z, vb.w);
        }
        __syncthreads();

#pragma unroll
        for (int ks = 0; ks < 2; ++ks) {
            const int kb2 = ks * 8;
            unsigned a[2][4], bf[8][2];
#pragma unroll
            for (int mt = 0; mt < 2; ++mt) {
                int m   = warp_m * 32 + mt * 16 + g;
                int rot = 2 * (m & 7);
                a[mt][0] = As[m * 16       + ((kb2 + tg     + rot) & 15)];
                a[mt][1] = As[(m + 8) * 16 + ((kb2 + tg     + rot) & 15)];
                a[mt][2] = As[m * 16       + ((kb2 + tg + 4 + rot) & 15)];
                a[mt][3] = As[(m + 8) * 16 + ((kb2 + tg + 4 + rot) & 15)];
            }
#pragma unroll
            for (int nt = 0; nt < 8; ++nt) {
                int n   = warp_n * 64 + nt * 8 + g;
                int rot = 2 * (n & 7);
                bf[nt][0] = Bs[n * 16 + ((kb2 + tg     + rot) & 15)];
                bf[nt][1] = Bs[n * 16 + ((kb2 + tg + 4 + rot) & 15)];
            }
#pragma unroll
            for (int mt = 0; mt < 2; ++mt)
#pragma unroll
                for (int nt = 0; nt < 8; ++nt)
                    mma16(acc[mt][nt], a[mt][0], a[mt][1], a[mt][2], a[mt][3],
                          bf[nt][0], bf[nt][1]);
        }
        __syncthreads();
    }

    // epilogue: add bias, write g_xp, mask m tail (MTOT = 16352)
#pragma unroll
    for (int mt = 0; mt < 2; ++mt) {
#pragma unroll
        for (int nt = 0; nt < 8; ++nt) {
            int m0 = mb * 64 + warp_m * 32 + mt * 16 + g;
            int n0 = nb * 256 + warp_n * 64 + nt * 8 + tg * 2;
            float bia0 = b_ih[n0] + b_hh[n0];
            float bia1 = b_ih[n0 + 1] + b_hh[n0 + 1];
            if (m0 < MTOT) {
                g_xp[(size_t)m0 * NGATE + n0]     = acc[mt][nt][0] + bia0;
                g_xp[(size_t)m0 * NGATE + n0 + 1] = acc[mt][nt][1] + bia1;
            }
            if (m0 + 8 < MTOT) {
                g_xp[(size_t)(m0 + 8) * NGATE + n0]     = acc[mt][nt][2] + bia0;
                g_xp[(size_t)(m0 + 8) * NGATE + n0 + 1] = acc[mt][nt][3] + bia1;
            }
        }
    }
}

// ---------------- persistent recurrent kernel --------------------------------
// 128 CTAs x 256 threads (R11 structure, measured best).
// Per-step sync: single-counter barrier. Arrival = red.release.gpu (fence
// folded into the atomic; cumulative over the preceding __syncthreads).
// Detection = tid0 acquire-poll + __syncthreads (no extra fence: cross-CTA
// data reads are L2-path .cg/.cs, acquire+bar gives the happens-before).
__global__ void __launch_bounds__(256, 1)
lstm_kernel(const float* __restrict__ h0, const float* __restrict__ c0,
            const float* __restrict__ W_hh, float* __restrict__ out, int out_size)
{
    __shared__ float red[8448];   // idx(m,n,w) = (m*33+n)*8+w

    const int tid = threadIdx.x, lane = tid & 31, wid = tid >> 5;
    const int g = lane >> 2, tg = lane & 3;
    const int j0 = blockIdx.x * 8;
    const int b = tid >> 3, jj = tid & 7;           // this thread's cell (b, j0+jj)

    // ---- load this CTA's W_hh fragments into registers (fp16 pairs) ----
    unsigned bw[8][4][2];
#pragma unroll
    for (int s = 0; s < 8; ++s) {
#pragma unroll
        for (int nt = 0; nt < 4; ++nt) {
            int r = nt * 8 + g;                 // local gate-row 0..31
            int q = r >> 3, jr = r & 7;
            const float* wrow = W_hh + (size_t)(q * 1024 + j0 + jr) * 1024
                                     + wid * 128 + s * 16;
            bw[s][nt][0] = pack_h2(wrow[2 * tg],     wrow[2 * tg + 1]);
            bw[s][nt][1] = pack_h2(wrow[8 + 2 * tg], wrow[8 + 2 * tg + 1]);
        }
    }

    float c_reg = c0[b * 1024 + j0 + jj];
    float* out_cell = out + ((size_t)b * TSTEPS) * 1024 + j0 + jj;

    // own h u32 slot (paired: jj-even thread stores both halves for jj, jj+1)
    const int hk     = j0 + jj;
    const int hp_idx = hp16_index(b, hk);

    // ---- prologue: pack own h0 slice (paired 4B stores), arrive ----
    {
        __half hh = __float2half(h0[b * 1024 + hk]);
        unsigned hu = (unsigned)__half_as_ushort(hh);
        unsigned up = __shfl_down_sync(0xffffffffu, hu, 1);
        if ((jj & 1) == 0) g_hp[0][hp_idx] = hu | (up << 16);
    }
    __syncthreads();
    if (tid == 0) red_release_add(&g_cnt, 1u);

    for (int t = 0; t < TSTEPS; ++t) {
        const unsigned* hb = g_hp[t & 1];

        // prefetch gate pre-activations (streaming; consumed after mma phase)
        float xpv[4];
        const float* xprow = &g_xp[(size_t)(t * 32 + b) * NGATE + j0 + jj];
#pragma unroll
        for (int q = 0; q < 4; ++q) xpv[q] = __ldcs(xprow + q * 1024);

        // wait until all 128 CTAs have published h_t: counter >= 128*(t+1)
        if (tid == 0) {
            const unsigned target = 128u * (unsigned)(t + 1);
            while ((int)(ldacq(&g_cnt) - target) < 0) { }
        }
        __syncthreads();

        // mma phase: warp wid owns k16 blocks wid*8 .. wid*8+7
        float C[8][4];
#pragma unroll
        for (int i = 0; i < 8; ++i) { C[i][0] = 0.f; C[i][1] = 0.f; C[i][2] = 0.f; C[i][3] = 0.f; }

#pragma unroll
        for (int s = 0; s < 8; ++s) {
            const unsigned* p = hb + ((wid * 8 + s) * 32 + lane) * 8;
            uint4 A0 = ldcg4(p);        // batches 0..15
            uint4 A1 = ldcg4(p + 4);    // batches 16..31
#pragma unroll
            for (int nt = 0; nt < 4; ++nt) {
                mma16(C[nt],     A0.x, A0.y, A0.z, A0.w, bw[s][nt][0], bw[s][nt][1]);
                mma16(C[4 + nt], A1.x, A1.y, A1.z, A1.w, bw[s][nt][0], bw[s][nt][1]);
            }
        }

        // K-split partials -> SMEM
#pragma unroll
        for (int mt = 0; mt < 2; ++mt) {
#pragma unroll
            for (int nt = 0; nt < 4; ++nt) {
                float* cc = C[mt * 4 + nt];
                int m  = mt * 16 + g;
                int n0 = nt * 8 + tg * 2;
                red[((m)     * 33 + n0    ) * 8 + wid] = cc[0];
                red[((m)     * 33 + n0 + 1) * 8 + wid] = cc[1];
                red[((m + 8) * 33 + n0    ) * 8 + wid] = cc[2];
                red[((m + 8) * 33 + n0 + 1) * 8 + wid] = cc[3];
            }
        }
        __syncthreads();   // partials visible

        // gate math: one thread per (b, jj)
        float z[4];
#pragma unroll
        for (int q = 0; q < 4; ++q) {
            int r = q * 8 + jj;
            const float4* p = (const float4*)&red[(b * 33 + r) * 8];
            float4 s0 = p[0], s1 = p[1];
            z[q] = xpv[q] + (((s0.x + s0.y) + (s0.z + s0.w)) +
                             ((s1.x + s1.y) + (s1.z + s1.w)));
        }
        float iv = fsig(z[0]);
        float fv = fsig(z[1]);
        float gv = ftanh(z[2]);
        float ov = fsig(z[3]);
        c_reg = fv * c_reg + iv * gv;
        float hv = ov * ftanh(c_reg);

        if (t < TSTEPS - 1) {
            // publish packed h_{t+1} (paired 4B stores) FIRST, then arrive
            __half hh = __float2half(hv);
            unsigned hu = (unsigned)__half_as_ushort(hh);
            unsigned up = __shfl_down_sync(0xffffffffu, hu, 1);
            if ((jj & 1) == 0) g_hp[(t + 1) & 1][hp_idx] = hu | (up << 16);
            __syncthreads();   // h stores done + red reuse safety
            if (tid == 0) red_release_add(&g_cnt, 1u);
            // streaming output store overlaps the next step's wait
            __stcs(out_cell + (size_t)t * 1024, hv);
        } else {
            __stcs(out_cell + (size_t)t * 1024, hv);
            if (out_size >= RES_ELEMS + 2 * BATCH * HID) {
                out[RES_ELEMS + b * 1024 + j0 + jj]               = hv;     // hT
                out[RES_ELEMS + BATCH * HID + b * 1024 + j0 + jj] = c_reg;  // cT
            }
        }
    }
}

// ---------------- launch ------------------------------------------------------
extern "C" void kernel_launch(void* const* d_in, const int* in_sizes, int n_in,
                              void* d_out, int out_size)
{
    const int*   tgt  = (const int*)  d_in[0];
    const float* h0   = (const float*)d_in[1];
    const float* c0   = (const float*)d_in[2];
    // d_in[3] encoder_outputs, d_in[4] src_lengths: unused by the reference
    const float* emb  = (const float*)d_in[5];
    const float* W_ih = (const float*)d_in[6];
    const float* W_hh = (const float*)d_in[7];
    const float* b_ih = (const float*)d_in[8];
    const float* b_hh = (const float*)d_in[9];
    float* out = (float*)d_out;

    dim3 grid_x(16, 256);                 // (n blocks of 256, m blocks of 64)
    xproj_kernel<<<grid_x, 256>>>(tgt, emb, W_ih, b_ih, b_hh);

    lstm_kernel<<<128, 256>>>(h0, c0, W_hh, out, out_size);
}

// round 14
// speedup vs baseline: 1.8245x; 1.0422x over previous
#include <cuda_runtime.h>
#include <cuda_fp16.h>
#include <cstdint>

// Problem constants
#define BATCH   32
#define HID     1024
#define NGATE   4096          // 4*HID
#define TSTEPS  511           // T-1
#define MTOT    16352         // TSTEPS*BATCH
#define RES_ELEMS (511*32*1024)

// ---------------- device scratch (no runtime allocation allowed) -------------
__device__ float    g_xp[(size_t)MTOT * NGATE];    // x-projection (+bias), fp32
__device__ unsigned g_hp[2][64 * 32 * 8];          // h double-buffered, fp16 frag-packed
__device__ unsigned g_cnt;                         // single barrier counter (reset by prew)
// pre-swizzled fp16 operand tiles for xproj (exact SMEM layout, copy-only load)
__device__ __align__(16) unsigned g_w16[(size_t)16 * 32 * 256 * 16];   // (nb,kt,m,slot) 8 MB
__device__ __align__(16) unsigned g_a16[(size_t)256 * 32 * 64 * 16];   // (mb,kt,m,slot) 33.5 MB

// ---------------- small helpers ----------------------------------------------
__device__ __forceinline__ uint4 ldcg4(const unsigned* p) {
    uint4 v;
    asm volatile("ld.global.cg.v4.u32 {%0,%1,%2,%3}, [%4];"
                 : "=r"(v.x), "=r"(v.y), "=r"(v.z), "=r"(v.w) : "l"(p));
    return v;
}
__device__ __forceinline__ unsigned ldacq(const unsigned* p) {
    unsigned v;
    asm volatile("ld.acquire.gpu.global.u32 %0, [%1];" : "=r"(v) : "l"(p));
    return v;
}
// fire-and-forget release reduction (fence folded into the atomic)
__device__ __forceinline__ void red_release_add(unsigned* p, unsigned v) {
    asm volatile("red.release.gpu.global.add.u32 [%0], %1;" :: "l"(p), "r"(v) : "memory");
}
// fp16 mma
__device__ __forceinline__ void mma16(float c[4], unsigned a0, unsigned a1, unsigned a2,
                                      unsigned a3, unsigned b0, unsigned b1) {
    asm volatile(
        "mma.sync.aligned.m16n8k16.row.col.f32.f16.f16.f32 "
        "{%0,%1,%2,%3}, {%4,%5,%6,%7}, {%8,%9}, {%0,%1,%2,%3};"
        : "+f"(c[0]), "+f"(c[1]), "+f"(c[2]), "+f"(c[3])
        : "r"(a0), "r"(a1), "r"(a2), "r"(a3), "r"(b0), "r"(b1));
}
__device__ __forceinline__ unsigned pack_h2(float x, float y) {
    __half2 h = __floats2half2_rn(x, y);
    return *(unsigned*)&h;
}
__device__ __forceinline__ float fsig(float x) {
    return __fdividef(1.f, 1.f + __expf(-x));
}
__device__ __forceinline__ float ftanh(float x) {
    return __fmaf_rn(2.f, fsig(2.f * x), -1.f);
}
// fp16 fragment-pack u32-slot index for h element (b, k); (k&1) selects the half.
__device__ __forceinline__ int hp16_index(int b, int k) {
    int kb   = k >> 4;
    int d    = (k >> 3) & 1;
    int tg   = (k >> 1) & 3;
    int g    = b & 7;
    int q    = b >> 3;
    int slot = ((q >> 1) << 2) | (d << 1) | (q & 1);
    int ln   = g * 4 + tg;
    return (kb * 32 + ln) * 8 + slot;
}
// SMEM tile slot for row m, k-pair p2 (0..15): matches consumer (kb2+tg+2*(m&7))&15
__device__ __forceinline__ int tile_slot(int m, int p2) {
    return 2 * ((((p2 >> 1) + m) & 7)) + (p2 & 1);
}

// ---------------- pre-pass: W_ih -> fp16, pre-swizzled tile layout ------------
// Also resets the lstm barrier counter (stream-ordered before lstm).
__global__ void __launch_bounds__(256)
prew_kernel(const float* __restrict__ W)
{
    if (blockIdx.x == 0 && threadIdx.x == 0) g_cnt = 0u;
    int idx = blockIdx.x * 256 + threadIdx.x;      // 4096*512 total
    int row = idx >> 9;                            // W_ih row (gate)
    int p   = idx & 511;                           // k-pair 0..511
    int nb = row >> 8, m = row & 255;
    int kt = p >> 4,  p2 = p & 15;
    unsigned val = pack_h2(W[(size_t)row * 1024 + 2 * p], W[(size_t)row * 1024 + 2 * p + 1]);
    g_w16[(((size_t)(nb * 32 + kt)) * 256 + m) * 16 + tile_slot(m, p2)] = val;
}

// ---------------- pre-pass: gathered emb rows -> fp16, pre-swizzled -----------
__global__ void __launch_bounds__(256)
prea_kernel(const int* __restrict__ tgt, const float* __restrict__ emb)
{
    int idx = blockIdx.x * 256 + threadIdx.x;      // 16384*512 total
    int mg = idx >> 9;                             // global m row (t*32+b)
    int p  = idx & 511;
    int bb = mg & 31, tt = mg >> 5;
    int tok = tgt[bb * 512 + tt];
    if (tok < 0 || tok > 31999) tok = 0;
    int mb = mg >> 6, m = mg & 63;
    int kt = p >> 4,  p2 = p & 15;
    unsigned val = pack_h2(emb[(size_t)tok * 1024 + 2 * p], emb[(size_t)tok * 1024 + 2 * p + 1]);
    g_a16[(((size_t)(mb * 32 + kt)) * 64 + m) * 16 + tile_slot(m, p2)] = val;
}

// ---------------- x_proj: xp[t*32+b][g] = emb[tgt[b][t]] . W_ih[g] + bias ----
// fp16 m16n8k16 GEMM, BM=64, BN=256, BK=32, 2 CTAs/SM. Loads are pure
// coalesced copies of pre-swizzled tiles (zero ALU in the load path).
__global__ void __launch_bounds__(256, 2)
xproj_kernel(const float* __restrict__ b_ih, const float* __restrict__ b_hh)
{
    __shared__ __align__(16) unsigned As[64 * 16];    // 4 KB
    __shared__ __align__(16) unsigned Bs[256 * 16];   // 16 KB

    const int nb = blockIdx.x, mb = blockIdx.y;
    const int tid = threadIdx.x, lane = tid & 31, wid = tid >> 5;
    const int warp_m = wid & 1, warp_n = wid >> 1;
    const int g = lane >> 2, tg = lane & 3;

    float acc[2][8][4];
#pragma unroll
    for (int mt = 0; mt < 2; ++mt)
#pragma unroll
        for (int nt = 0; nt < 8; ++nt)
#pragma unroll
            for (int i = 0; i < 4; ++i) acc[mt][nt][i] = 0.f;

    const unsigned* abase = g_a16 + (size_t)(mb * 32) * 64 * 16;
    const unsigned* wbase = g_w16 + (size_t)(nb * 32) * 256 * 16;

    for (int kt = 0; kt < 32; ++kt) {
        const unsigned* at = abase + (size_t)kt * 64 * 16;
        const unsigned* wt = wbase + (size_t)kt * 256 * 16;
        // A tile: 1024 u32 (one uint4 per thread)
        *(uint4*)&As[tid * 4] = *(const uint4*)&at[tid * 4];
        // B tile: 4096 u32 (four uint4 per thread, coalesced)
#pragma unroll
        for (int i = 0; i < 4; ++i)
            *(uint4*)&Bs[(i * 256 + tid) * 4] = *(const uint4*)&wt[(i * 256 + tid) * 4];
        __syncthreads();

#pragma unroll
        for (int ks = 0; ks < 2; ++ks) {
            const int kb2 = ks * 8;
            unsigned a[2][4], bf[8][2];
#pragma unroll
            for (int mt = 0; mt < 2; ++mt) {
                int m   = warp_m * 32 + mt * 16 + g;
                int rot = 2 * (m & 7);
                a[mt][0] = As[m * 16       + ((kb2 + tg     + rot) & 15)];
                a[mt][1] = As[(m + 8) * 16 + ((kb2 + tg     + rot) & 15)];
                a[mt][2] = As[m * 16       + ((kb2 + tg + 4 + rot) & 15)];
                a[mt][3] = As[(m + 8) * 16 + ((kb2 + tg + 4 + rot) & 15)];
            }
#pragma unroll
            for (int nt = 0; nt < 8; ++nt) {
                int n   = warp_n * 64 + nt * 8 + g;
                int rot = 2 * (n & 7);
                bf[nt][0] = Bs[n * 16 + ((kb2 + tg     + rot) & 15)];
                bf[nt][1] = Bs[n * 16 + ((kb2 + tg + 4 + rot) & 15)];
            }
#pragma unroll
            for (int mt = 0; mt < 2; ++mt)
#pragma unroll
                for (int nt = 0; nt < 8; ++nt)
                    mma16(acc[mt][nt], a[mt][0], a[mt][1], a[mt][2], a[mt][3],
                          bf[nt][0], bf[nt][1]);
        }
        __syncthreads();
    }

    // epilogue: add bias, write g_xp, mask m tail (MTOT = 16352)
#pragma unroll
    for (int mt = 0; mt < 2; ++mt) {
#pragma unroll
        for (int nt = 0; nt < 8; ++nt) {
            int m0 = mb * 64 + warp_m * 32 + mt * 16 + g;
            int n0 = nb * 256 + warp_n * 64 + nt * 8 + tg * 2;
            float bia0 = b_ih[n0] + b_hh[n0];
            float bia1 = b_ih[n0 + 1] + b_hh[n0 + 1];
            if (m0 < MTOT) {
                g_xp[(size_t)m0 * NGATE + n0]     = acc[mt][nt][0] + bia0;
                g_xp[(size_t)m0 * NGATE + n0 + 1] = acc[mt][nt][1] + bia1;
            }
            if (m0 + 8 < MTOT) {
                g_xp[(size_t)(m0 + 8) * NGATE + n0]     = acc[mt][nt][2] + bia0;
                g_xp[(size_t)(m0 + 8) * NGATE + n0 + 1] = acc[mt][nt][3] + bia1;
            }
        }
    }
}

// ---------------- persistent recurrent kernel --------------------------------
// 128 CTAs x 256 threads (R13 structure, measured best; sync scheme frozen).
// Change vs R13: out stores staged in SMEM and issued as 64 x STG.128.cs
// (4x fewer L1TEX wavefronts feeding the next step's critical loads).
__global__ void __launch_bounds__(256, 1)
lstm_kernel(const float* __restrict__ h0, const float* __restrict__ c0,
            const float* __restrict__ W_hh, float* __restrict__ out, int out_size)
{
    __shared__ float red[8448];    // idx(m,n,w) = (m*33+n)*8+w
    __shared__ float stage[256];   // hv staging for coalesced out stores

    const int tid = threadIdx.x, lane = tid & 31, wid = tid >> 5;
    const int g = lane >> 2, tg = lane & 3;
    const int j0 = blockIdx.x * 8;
    const int b = tid >> 3, jj = tid & 7;           // this thread's cell (b, j0+jj)

    // ---- load this CTA's W_hh fragments into registers (fp16 pairs) ----
    unsigned bw[8][4][2];
#pragma unroll
    for (int s = 0; s < 8; ++s) {
#pragma unroll
        for (int nt = 0; nt < 4; ++nt) {
            int r = nt * 8 + g;                 // local gate-row 0..31
            int q = r >> 3, jr = r & 7;
            const float* wrow = W_hh + (size_t)(q * 1024 + j0 + jr) * 1024
                                     + wid * 128 + s * 16;
            bw[s][nt][0] = pack_h2(wrow[2 * tg],     wrow[2 * tg + 1]);
            bw[s][nt][1] = pack_h2(wrow[8 + 2 * tg], wrow[8 + 2 * tg + 1]);
        }
    }

    float c_reg = c0[b * 1024 + j0 + jj];

    // own h u32 slot (paired: jj-even thread stores both halves for jj, jj+1)
    const int hk     = j0 + jj;
    const int hp_idx = hp16_index(b, hk);

    // ---- prologue: pack own h0 slice (paired 4B stores), arrive ----
    {
        __half hh = __float2half(h0[b * 1024 + hk]);
        unsigned hu = (unsigned)__half_as_ushort(hh);
        unsigned up = __shfl_down_sync(0xffffffffu, hu, 1);
        if ((jj & 1) == 0) g_hp[0][hp_idx] = hu | (up << 16);
    }
    __syncthreads();
    if (tid == 0) red_release_add(&g_cnt, 1u);

    for (int t = 0; t < TSTEPS; ++t) {
        const unsigned* hb = g_hp[t & 1];

        // prefetch gate pre-activations (streaming; consumed after mma phase)
        float xpv[4];
        const float* xprow = &g_xp[(size_t)(t * 32 + b) * NGATE + j0 + jj];
#pragma unroll
        for (int q = 0; q < 4; ++q) xpv[q] = __ldcs(xprow + q * 1024);

        // wait until all 128 CTAs have published h_t: counter >= 128*(t+1)
        if (tid == 0) {
            const unsigned target = 128u * (unsigned)(t + 1);
            while ((int)(ldacq(&g_cnt) - target) < 0) { }
        }
        __syncthreads();

        // mma phase: warp wid owns k16 blocks wid*8 .. wid*8+7
        float C[8][4];
#pragma unroll
        for (int i = 0; i < 8; ++i) { C[i][0] = 0.f; C[i][1] = 0.f; C[i][2] = 0.f; C[i][3] = 0.f; }

#pragma unroll
        for (int s = 0; s < 8; ++s) {
            const unsigned* p = hb + ((wid * 8 + s) * 32 + lane) * 8;
            uint4 A0 = ldcg4(p);        // batches 0..15
            uint4 A1 = ldcg4(p + 4);    // batches 16..31
#pragma unroll
            for (int nt = 0; nt < 4; ++nt) {
                mma16(C[nt],     A0.x, A0.y, A0.z, A0.w, bw[s][nt][0], bw[s][nt][1]);
                mma16(C[4 + nt], A1.x, A1.y, A1.z, A1.w, bw[s][nt][0], bw[s][nt][1]);
            }
        }

        // K-split partials -> SMEM
#pragma unroll
        for (int mt = 0; mt < 2; ++mt) {
#pragma unroll
            for (int nt = 0; nt < 4; ++nt) {
                float* cc = C[mt * 4 + nt];
                int m  = mt * 16 + g;
                int n0 = nt * 8 + tg * 2;
                red[((m)     * 33 + n0    ) * 8 + wid] = cc[0];
                red[((m)     * 33 + n0 + 1) * 8 + wid] = cc[1];
                red[((m + 8) * 33 + n0    ) * 8 + wid] = cc[2];
                red[((m + 8) * 33 + n0 + 1) * 8 + wid] = cc[3];
            }
        }
        __syncthreads();   // partials visible

        // gate math: one thread per (b, jj)
        float z[4];
#pragma unroll
        for (int q = 0; q < 4; ++q) {
            int r = q * 8 + jj;
            const float4* p = (const float4*)&red[(b * 33 + r) * 8];
            float4 s0 = p[0], s1 = p[1];
            z[q] = xpv[q] + (((s0.x + s0.y) + (s0.z + s0.w)) +
                             ((s1.x + s1.y) + (s1.z + s1.w)));
        }
        float iv = fsig(z[0]);
        float fv = fsig(z[1]);
        float gv = ftanh(z[2]);
        float ov = fsig(z[3]);
        c_reg = fv * c_reg + iv * gv;
        float hv = ov * ftanh(c_reg);

        if (t < TSTEPS - 1) {
            // stage hv; publish packed h_{t+1} (paired 4B stores); then arrive
            stage[tid] = hv;
            __half hh = __float2half(hv);
            unsigned hu = (unsigned)__half_as_ushort(hh);
            unsigned up = __shfl_down_sync(0xffffffffu, hu, 1);
            if ((jj & 1) == 0) g_hp[(t + 1) & 1][hp_idx] = hu | (up << 16);
            __syncthreads();   // h + stage visible, red reuse safety
            if (tid == 0) red_release_add(&g_cnt, 1u);
            // coalesced out stores (off the critical path, overlap next wait)
            if (tid < 64) {
                int bb = tid >> 1, half = tid & 1;
                float4 v = *(const float4*)&stage[bb * 8 + half * 4];
                float* dst = out + ((size_t)bb * TSTEPS + t) * 1024 + j0 + half * 4;
                __stcs((float4*)dst, v);
            }
        } else {
            __stcs(out + ((size_t)b * TSTEPS + t) * 1024 + j0 + jj, hv);
            if (out_size >= RES_ELEMS + 2 * BATCH * HID) {
                out[RES_ELEMS + b * 1024 + j0 + jj]               = hv;     // hT
                out[RES_ELEMS + BATCH * HID + b * 1024 + j0 + jj] = c_reg;  // cT
            }
        }
    }
}

// ---------------- launch ------------------------------------------------------
extern "C" void kernel_launch(void* const* d_in, const int* in_sizes, int n_in,
                              void* d_out, int out_size)
{
    const int*   tgt  = (const int*)  d_in[0];
    const float* h0   = (const float*)d_in[1];
    const float* c0   = (const float*)d_in[2];
    // d_in[3] encoder_outputs, d_in[4] src_lengths: unused by the reference
    const float* emb  = (const float*)d_in[5];
    const float* W_ih = (const float*)d_in[6];
    const float* W_hh = (const float*)d_in[7];
    const float* b_ih = (const float*)d_in[8];
    const float* b_hh = (const float*)d_in[9];
    float* out = (float*)d_out;

    prew_kernel<<<4096 * 512 / 256, 256>>>(W_ih);          // W -> fp16 tiles (+cnt reset)
    prea_kernel<<<16384 * 512 / 256, 256>>>(tgt, emb);     // emb gather -> fp16 tiles

    dim3 grid_x(16, 256);                 // (n blocks of 256, m blocks of 64)
    xproj_kernel<<<grid_x, 256>>>(b_ih, b_hh);

    lstm_kernel<<<128, 256>>>(h0, c0, W_hh, out, out_size);
}